// round 7
// baseline (speedup 1.0000x reference)
#include <cuda_runtime.h>
#include <cstdint>
#include <cfloat>

#define B_  32
#define K_  17
#define H_  192
#define W_  192
#define C_  19
#define P_  20
#define S_  10
#define HW_ (H_*W_)
#define NCH (B_*K_)

#define PEAK_THRESH      0.1f
#define PAF_SCORE_THRESH 0.05f
#define PAF_COUNT_THRESH 0.8f

#define CAND_CAP 5120
#define SURV_CAP 512
#define NBINS    256
#define CTA_BUF  1536     // expected ~683 peaks per 32-row CTA

#define OX   24           // octs per row (192/8)
#define TY   8            // thread rows per CTA
#define RPT  4            // pixel rows per thread
#define CTAROWS (TY*RPT)  // 32 rows per CTA
#define NTS  (OX*TY)      // 192 threads

__constant__ int SKEL_A[C_] = {15,13,16,14,11, 5, 6, 5, 5, 6, 7, 8, 1, 0, 0, 1, 2, 3, 4};
__constant__ int SKEL_B[C_] = {13,11,14,12,12,11,12, 6, 7, 8, 9,10, 2, 1, 2, 3, 4, 5, 6};

// global scratch (zero-initialized at load; select restores zeros each run)
__device__ unsigned long long g_keys[NCH][CAND_CAP];
__device__ int g_count[NCH];
__device__ int g_hist[NCH][NBINS];

__device__ __forceinline__ float fmax3(float a, float b, float c) {
    return fmaxf(a, fmaxf(b, c));
}

// ---------------------------------------------------------------------------
// Kernel 1a: streaming peak scan. Thread = 8x4 pixel block, rolling rows.
// ---------------------------------------------------------------------------
__global__ __launch_bounds__(NTS)
void peaks_scan(const float* __restrict__ heat)
{
    const int bk = blockIdx.y;
    const float* __restrict__ h = heat + (size_t)bk * HW_;

    const int ox  = threadIdx.x;                        // 0..23
    const int y0  = blockIdx.x * CTAROWS + threadIdx.y * RPT;
    const int tid = threadIdx.y * OX + threadIdx.x;
    const int lane = tid & 31;
    const int x0  = ox * 8;

    __shared__ unsigned long long s_buf[CTA_BUF];
    __shared__ int s_hist[NBINS];
    __shared__ int s_cnt;
    __shared__ int s_gbase;

    for (int i = tid; i < NBINS; i += NTS) s_hist[i] = 0;
    if (tid == 0) s_cnt = 0;
    __syncthreads();

    const bool has_l = (ox > 0);
    const bool has_r = (ox < OX - 1);
    const float4 NEG4 = make_float4(-FLT_MAX, -FLT_MAX, -FLT_MAX, -FLT_MAX);

    // rolling state: rows y-1 (aL/aH) and y (bL/bH)
    float4 aL, aH, bL, bH;
    float la, ra, lb, rb;
    {
        const float* rw = h + (size_t)y0 * W_;
        bL = __ldg((const float4*)rw + 2*ox);
        bH = __ldg((const float4*)rw + 2*ox + 1);
        lb = has_l ? __ldg(rw + x0 - 1) : -FLT_MAX;
        rb = has_r ? __ldg(rw + x0 + 8) : -FLT_MAX;
        if (y0 > 0) {
            const float* ru = rw - W_;
            aL = __ldg((const float4*)ru + 2*ox);
            aH = __ldg((const float4*)ru + 2*ox + 1);
            la = has_l ? __ldg(ru + x0 - 1) : -FLT_MAX;
            ra = has_r ? __ldg(ru + x0 + 8) : -FLT_MAX;
        } else {
            aL = NEG4; aH = NEG4; la = -FLT_MAX; ra = -FLT_MAX;
        }
    }

    #pragma unroll
    for (int r = 0; r < RPT; r++) {
        const int y = y0 + r;
        float4 cL, cH; float lc, rc;
        if (y + 1 < H_) {
            const float* rd = h + (size_t)(y + 1) * W_;
            cL = __ldg((const float4*)rd + 2*ox);
            cH = __ldg((const float4*)rd + 2*ox + 1);
            lc = has_l ? __ldg(rd + x0 - 1) : -FLT_MAX;
            rc = has_r ? __ldg(rd + x0 + 8) : -FLT_MAX;
        } else {
            cL = NEG4; cH = NEG4; lc = -FLT_MAX; rc = -FLT_MAX;
        }

        // vertical 3-max per column
        float v[8];
        v[0] = fmax3(aL.x, bL.x, cL.x);
        v[1] = fmax3(aL.y, bL.y, cL.y);
        v[2] = fmax3(aL.z, bL.z, cL.z);
        v[3] = fmax3(aL.w, bL.w, cL.w);
        v[4] = fmax3(aH.x, bH.x, cH.x);
        v[5] = fmax3(aH.y, bH.y, cH.y);
        v[6] = fmax3(aH.z, bH.z, cH.z);
        v[7] = fmax3(aH.w, bH.w, cH.w);
        float vl = fmax3(la, lb, lc);
        float vr = fmax3(ra, rb, rc);

        // horizontal windows: w[i] = max(pair(i-1,i), v[i+1])
        float pm[8];                       // pm[i] = max(v[i-1], v[i])
        pm[0] = fmaxf(vl, v[0]);
        #pragma unroll
        for (int i = 1; i < 8; i++) pm[i] = fmaxf(v[i-1], v[i]);
        float w[8];
        #pragma unroll
        for (int i = 0; i < 7; i++) w[i] = fmaxf(pm[i], v[i+1]);
        w[7] = fmaxf(pm[7], vr);

        float vv[8] = {bL.x, bL.y, bL.z, bL.w, bH.x, bH.y, bH.z, bH.w};

        bool pk[8];
        unsigned mm[8];
        int total = 0;
        #pragma unroll
        for (int c = 0; c < 8; c++) {
            pk[c] = (vv[c] > PEAK_THRESH) && (vv[c] >= w[c]);
            mm[c] = __ballot_sync(0xffffffffu, pk[c]);
            total += __popc(mm[c]);
        }

        if (total) {   // warp-uniform
            int base = 0;
            if (lane == 0) base = atomicAdd(&s_cnt, total);
            base = __shfl_sync(0xffffffffu, base, 0);
            const unsigned lt = (1u << lane) - 1u;
            const int prow = y * W_ + x0;
            int cum = 0;
            #pragma unroll
            for (int c = 0; c < 8; c++) {
                if (pk[c]) {
                    int pos = base + cum + __popc(mm[c] & lt);
                    if (pos < CTA_BUF) {
                        float vvc = vv[c];
                        s_buf[pos] =
                            ((unsigned long long)__float_as_uint(vvc) << 32)
                            | (unsigned)(0xFFFFFFFFu - (unsigned)(prow + c));
                        atomicAdd(&s_hist[min(NBINS-1, (int)(vvc * (float)NBINS))], 1);
                    }
                }
                cum += __popc(mm[c]);
            }
        }

        // shift rolling window
        aL = bL; aH = bH; bL = cL; bH = cH;
        la = lb; lb = lc;
        ra = rb; rb = rc;
    }
    __syncthreads();

    const int n = min(s_cnt, CTA_BUF);
    if (tid == 0 && n > 0) s_gbase = atomicAdd(&g_count[bk], n);
    __syncthreads();

    if (n > 0) {
        const int gbase = s_gbase;
        for (int i = tid; i < n; i += NTS) {
            int pos = gbase + i;
            if (pos < CAND_CAP) g_keys[bk][pos] = s_buf[i];
        }
    }
    for (int i = tid; i < NBINS; i += NTS) {
        int hv = s_hist[i];
        if (hv) atomicAdd(&g_hist[bk][i], hv);   // fire-and-forget RED
    }
}

// ---------------------------------------------------------------------------
// Kernel 1b: per-channel top-20 selection (warp-0, shfl-only rounds)
//            + subpixel refine + scratch reset.
// ---------------------------------------------------------------------------
#define NT1 256
__global__ __launch_bounds__(NT1)
void peaks_select(const float* __restrict__ heat, float* __restrict__ out_peaks)
{
    const int bk = blockIdx.x;
    const float* __restrict__ h = heat + (size_t)bk * HW_;

    __shared__ unsigned long long surv[SURV_CAP];
    __shared__ int   s_hist[NBINS];
    __shared__ int   s_nsurv, s_tbin;
    __shared__ unsigned long long sel_key[P_];

    const int tid  = threadIdx.x;
    const int lane = tid & 31;
    const int wid  = tid >> 5;

    const int nc = min(g_count[bk], CAND_CAP);

    s_hist[tid] = g_hist[bk][tid];
    if (tid == 0) s_nsurv = 0;
    __syncthreads();

    if (tid == 0) {
        int need = min(P_, nc);
        int cum = 0, t = 0;
        if (need > 0) {
            for (int b = NBINS - 1; b >= 0; --b) {
                cum += s_hist[b];
                if (cum >= need) { t = b; break; }
            }
        }
        s_tbin = t;
    }
    __syncthreads();
    const int tbin = s_tbin;

    for (int i = tid; i < nc; i += NT1) {
        unsigned long long k = g_keys[bk][i];
        float sc = __uint_as_float((unsigned)(k >> 32));
        int bin = min(NBINS - 1, (int)(sc * (float)NBINS));
        if (bin >= tbin) {
            int slot = atomicAdd(&s_nsurv, 1);
            if (slot < SURV_CAP) surv[slot] = k;
        }
    }
    __syncthreads();

    if (wid == 0) {
        unsigned long long* list;
        int len;
        if (s_nsurv <= SURV_CAP) { list = surv; len = s_nsurv; }
        else                     { list = &g_keys[bk][0]; len = nc; }

        for (int r = 0; r < P_; r++) {
            unsigned long long bkey = 0ull;
            int bidx = -1;
            for (int i = lane; i < len; i += 32) {
                unsigned long long k = list[i];
                if (k > bkey) { bkey = k; bidx = i; }
            }
            #pragma unroll
            for (int o = 16; o > 0; o >>= 1) {
                unsigned long long ok = __shfl_down_sync(0xffffffffu, bkey, o);
                int oi = __shfl_down_sync(0xffffffffu, bidx, o);
                if (ok > bkey) { bkey = ok; bidx = oi; }
            }
            if (lane == 0) {
                sel_key[r] = bkey;
                if (bidx >= 0) list[bidx] = 0ull;
            }
            __syncwarp();
        }
    }
    __syncthreads();

    if (tid < P_) {
        unsigned long long k = sel_key[tid];
        float px = 0.0f, py = 0.0f, so = 0.0f;
        if (k != 0ull) {
            float sc = __uint_as_float((unsigned)(k >> 32));
            int p = (int)(0xFFFFFFFFu - (unsigned)(k & 0xFFFFFFFFull));
            int y = p / W_;
            int x = p - y * W_;
            float ddx = 0.0f, ddy = 0.0f;
            if (x > 0 && x < W_-1 && y > 0 && y < H_-1) {
                float c  = h[p];
                float rr = h[p + 1],  ll = h[p - 1];
                float dd = h[p + W_], uu = h[p - W_];
                float dx  = 0.5f * (rr - ll);
                float dxx = (rr + ll) - 2.0f * c;
                if (dxx != 0.0f) dx = dx / (-dxx);
                float dy  = 0.5f * (dd - uu);
                float dyy = (dd + uu) - 2.0f * c;
                if (dyy != 0.0f) dy = dy / (-dyy);
                ddx = dx; ddy = dy;
            }
            px = (float)x + ddx;
            py = (float)y + ddy;
            so = sc;
        }
        float* o = out_peaks + ((size_t)bk * P_ + tid) * 3;
        o[0] = px; o[1] = py; o[2] = so;
    }

    if (tid == 0) g_count[bk] = 0;
    g_hist[bk][tid] = 0;
}

// ---------------------------------------------------------------------------
// Kernel 2: flat one-thread-per-cell PAF line-integral scoring.
// ---------------------------------------------------------------------------
#define NT2 256
#define NCELLS (B_*C_*P_*P_)
__global__ __launch_bounds__(NT2)
void conn_kernel(const float* __restrict__ paf,
                 const float* __restrict__ peaks,
                 float* __restrict__ conn)
{
    const int gid = blockIdx.x * NT2 + threadIdx.x;
    if (gid >= NCELLS) return;

    int j = gid % P_;
    int t = gid / P_;
    int i = t % P_;  t /= P_;
    int c = t % C_;
    int b = t / C_;

    const float* pkA = peaks + (((size_t)b * K_ + SKEL_A[c]) * P_ + i) * 3;
    const float* pkB = peaks + (((size_t)b * K_ + SKEL_B[c]) * P_ + j) * 3;
    float axi = __ldg(pkA + 0), ayi = __ldg(pkA + 1), sa = __ldg(pkA + 2);
    float bxj = __ldg(pkB + 0), byj = __ldg(pkB + 1), sb = __ldg(pkB + 2);

    const float* __restrict__ pafx = paf + ((size_t)b * (2*C_) + 2*c) * HW_;
    const float* __restrict__ pafy = pafx + HW_;

    const float delta = 1.0f / 9.0f;

    float dxl = bxj - axi;
    float dyl = byj - ayi;
    float norm = sqrtf(dxl*dxl + dyl*dyl) + 1e-8f;
    float vx = dxl / norm, vy = dyl / norm;

    int   idx[S_];
    bool  inb[S_];
    #pragma unroll
    for (int s = 0; s < S_; s++) {
        float t2 = (s == S_-1) ? 1.0f : (float)s * delta;
        float xs = axi + dxl * t2;
        float ys = ayi + dyl * t2;
        int xi = __float2int_rz(xs);
        int yi = __float2int_rz(ys);
        inb[s] = (xi >= 0) & (xi < W_) & (yi >= 0) & (yi < H_);
        int xc = min(max(xi, 0), W_ - 1);
        int yc = min(max(yi, 0), H_ - 1);
        idx[s] = yc * W_ + xc;
    }

    float pxv[S_], pyv[S_];
    #pragma unroll
    for (int s = 0; s < S_; s++) pxv[s] = __ldg(pafx + idx[s]);
    #pragma unroll
    for (int s = 0; s < S_; s++) pyv[s] = __ldg(pafy + idx[s]);

    float cnt = 0.0f, sum = 0.0f, cntp = 0.0f;
    #pragma unroll
    for (int s = 0; s < S_; s++) {
        float vs = pxv[s] * vx + pyv[s] * vy;
        if (inb[s]) {
            cnt += 1.0f;
            sum += vs;
            if (vs > PAF_SCORE_THRESH) cntp += 1.0f;
        }
    }

    float denom = fmaxf(cnt, 1.0f);
    float mean  = sum / denom;
    float ratio = cntp / denom;
    bool ok = (cnt > 0.0f) && (mean > 0.0f) && (ratio > PAF_COUNT_THRESH)
              && (sa > PEAK_THRESH) && (sb > PEAK_THRESH);
    conn[gid] = ok ? (mean + 0.5f * (sa + sb)) : 0.0f;
}

// ---------------------------------------------------------------------------
extern "C" void kernel_launch(void* const* d_in, const int* in_sizes, int n_in,
                              void* d_out, int out_size)
{
    const float* heat = (const float*)d_in[0];
    const float* paf  = (const float*)d_in[1];
    if (n_in >= 2 && in_sizes[0] == B_ * 2 * C_ * HW_ && in_sizes[1] == B_ * K_ * HW_) {
        heat = (const float*)d_in[1];
        paf  = (const float*)d_in[0];
    }

    float* out_peaks = (float*)d_out;                      // B*K*P*3
    float* out_conn  = out_peaks + (size_t)B_ * K_ * P_ * 3;

    dim3 g1(H_ / CTAROWS, NCH);
    dim3 b1(OX, TY);
    peaks_scan<<<g1, b1>>>(heat);

    peaks_select<<<NCH, NT1>>>(heat, out_peaks);

    conn_kernel<<<(NCELLS + NT2 - 1) / NT2, NT2>>>(paf, out_peaks, out_conn);
}

// round 8
// speedup vs baseline: 1.0253x; 1.0253x over previous
#include <cuda_runtime.h>
#include <cstdint>
#include <cfloat>

#define B_  32
#define K_  17
#define H_  192
#define W_  192
#define C_  19
#define P_  20
#define S_  10
#define HW_ (H_*W_)
#define NCH (B_*K_)

#define PEAK_THRESH      0.1f
#define PAF_SCORE_THRESH 0.05f
#define PAF_COUNT_THRESH 0.8f

#define CAND_CAP 5120
#define SURV_CAP 512
#define NBINS    256
#define CTA_BUF  2048     // 64 rows * 192 px * ~0.115 ~ 1414 expected

#define QX   48           // quads per row (192/4)
#define TY   8            // thread rows per CTA
#define RPT  8            // pixel rows per thread
#define CTAROWS (TY*RPT)  // 64 rows per CTA
#define NTS  (QX*TY)      // 384 threads

__constant__ int SKEL_A[C_] = {15,13,16,14,11, 5, 6, 5, 5, 6, 7, 8, 1, 0, 0, 1, 2, 3, 4};
__constant__ int SKEL_B[C_] = {13,11,14,12,12,11,12, 6, 7, 8, 9,10, 2, 1, 2, 3, 4, 5, 6};

// global scratch (zero-initialized at load; select restores zeros each run)
__device__ unsigned long long g_keys[NCH][CAND_CAP];
__device__ int g_count[NCH];

__device__ __forceinline__ float fmax3(float a, float b, float c) {
    return fmaxf(a, fmaxf(b, c));
}

// ---------------------------------------------------------------------------
// Kernel 1a: streaming peak scan. Thread = 4x8 pixel block, rolling rows,
// shfl-sourced horizontal edges, no histogram.
// ---------------------------------------------------------------------------
__global__ __launch_bounds__(NTS)
void peaks_scan(const float* __restrict__ heat)
{
    const int bk = blockIdx.y;
    const float* __restrict__ h = heat + (size_t)bk * HW_;

    const int qx  = threadIdx.x;                        // 0..47
    const int y0  = blockIdx.x * CTAROWS + threadIdx.y * RPT;
    const int tid = threadIdx.y * QX + threadIdx.x;
    const int lane = tid & 31;
    const int x0  = qx * 4;

    __shared__ unsigned long long s_buf[CTA_BUF];
    __shared__ int s_cnt;
    __shared__ int s_gbase;

    if (tid == 0) s_cnt = 0;
    __syncthreads();

    // only these lanes need real edge-column loads; all others get edge
    // vertical-maxes from neighbor threads via shfl
    const bool is_l = (lane == 0)  && (qx > 0);
    const bool is_r = (lane == 31) && (qx < QX - 1);
    const float4 NEG4 = make_float4(-FLT_MAX, -FLT_MAX, -FLT_MAX, -FLT_MAX);
    const float THR = __uint_as_float(0x3DCCCCCEu);   // nextafter(0.1f, +inf)

    // rolling state: rows y-1 (a) and y (b); edge scalars only for is_l/is_r
    float4 a, b;
    float el_a = -FLT_MAX, el_b = -FLT_MAX;
    float er_a = -FLT_MAX, er_b = -FLT_MAX;
    {
        const float* rw = h + (size_t)y0 * W_;
        b = __ldg((const float4*)rw + qx);
        if (is_l) el_b = __ldg(rw + x0 - 1);
        if (is_r) er_b = __ldg(rw + x0 + 4);
        if (y0 > 0) {
            a = __ldg((const float4*)(rw - W_) + qx);
            if (is_l) el_a = __ldg(rw - W_ + x0 - 1);
            if (is_r) er_a = __ldg(rw - W_ + x0 + 4);
        } else {
            a = NEG4;
        }
    }

    #pragma unroll
    for (int r = 0; r < RPT; r++) {
        const int y = y0 + r;
        float4 c;
        float el_c = -FLT_MAX, er_c = -FLT_MAX;
        if (y + 1 < H_) {
            const float* rd = h + (size_t)(y + 1) * W_;
            c = __ldg((const float4*)rd + qx);
            if (is_l) el_c = __ldg(rd + x0 - 1);
            if (is_r) er_c = __ldg(rd + x0 + 4);
        } else {
            c = NEG4;
        }

        // vertical 3-max per column
        float v0 = fmax3(a.x, b.x, c.x);
        float v1 = fmax3(a.y, b.y, c.y);
        float v2 = fmax3(a.z, b.z, c.z);
        float v3 = fmax3(a.w, b.w, c.w);

        // edge vertical maxes from neighbor lanes (same image row by layout)
        float vl = __shfl_up_sync(0xffffffffu, v3, 1);
        if (lane == 0)   vl = fmax3(el_a, el_b, el_c);
        if (qx == 0)     vl = -FLT_MAX;
        float vr = __shfl_down_sync(0xffffffffu, v0, 1);
        if (lane == 31)  vr = fmax3(er_a, er_b, er_c);
        if (qx == QX-1)  vr = -FLT_MAX;

        // horizontal 3-windows with folded peak threshold
        float m01 = fmaxf(v0, v1);
        float m23 = fmaxf(v2, v3);
        float w0 = fmaxf(fmaxf(vl,  m01), THR);
        float w1 = fmaxf(fmaxf(m01, v2),  THR);
        float w2 = fmaxf(fmaxf(v1,  m23), THR);
        float w3 = fmaxf(fmaxf(m23, vr),  THR);

        const bool p0 = (b.x >= w0);
        const bool p1 = (b.y >= w1);
        const bool p2 = (b.z >= w2);
        const bool p3 = (b.w >= w3);

        unsigned m0 = __ballot_sync(0xffffffffu, p0);
        unsigned m1 = __ballot_sync(0xffffffffu, p1);
        unsigned m2 = __ballot_sync(0xffffffffu, p2);
        unsigned m3 = __ballot_sync(0xffffffffu, p3);
        int n0 = __popc(m0), n1 = __popc(m1), n2 = __popc(m2);
        int total = n0 + n1 + n2 + __popc(m3);

        if (total) {   // warp-uniform
            int base = 0;
            if (lane == 0) base = atomicAdd(&s_cnt, total);
            base = __shfl_sync(0xffffffffu, base, 0);
            const unsigned lt = (1u << lane) - 1u;
            const int prow = y * W_ + x0;
            #define STORE_PK(v, pos, pix)                                           \
                do { int _p = (pos);                                                \
                     if (_p < CTA_BUF)                                              \
                         s_buf[_p] = ((unsigned long long)__float_as_uint(v) << 32) \
                                   | (unsigned)(0xFFFFFFFFu - (unsigned)(pix));     \
                } while (0)
            if (p0) STORE_PK(b.x, base + __popc(m0 & lt),                prow);
            if (p1) STORE_PK(b.y, base + n0 + __popc(m1 & lt),           prow + 1);
            if (p2) STORE_PK(b.z, base + n0 + n1 + __popc(m2 & lt),      prow + 2);
            if (p3) STORE_PK(b.w, base + n0 + n1 + n2 + __popc(m3 & lt), prow + 3);
            #undef STORE_PK
        }

        // shift rolling window
        a = b; b = c;
        el_a = el_b; el_b = el_c;
        er_a = er_b; er_b = er_c;
    }
    __syncthreads();

    const int n = min(s_cnt, CTA_BUF);
    if (tid == 0 && n > 0) s_gbase = atomicAdd(&g_count[bk], n);
    __syncthreads();

    if (n > 0) {
        const int gbase = s_gbase;
        for (int i = tid; i < n; i += NTS) {
            int pos = gbase + i;
            if (pos < CAND_CAP) g_keys[bk][pos] = s_buf[i];
        }
    }
}

// ---------------------------------------------------------------------------
// Kernel 1b: per-channel top-20 selection. Builds its own histogram from the
// key list, warp-0 shfl-only argmax rounds, subpixel refine, scratch reset.
// ---------------------------------------------------------------------------
#define NT1 256
__global__ __launch_bounds__(NT1)
void peaks_select(const float* __restrict__ heat, float* __restrict__ out_peaks)
{
    const int bk = blockIdx.x;
    const float* __restrict__ h = heat + (size_t)bk * HW_;

    __shared__ unsigned long long surv[SURV_CAP];
    __shared__ int   s_hist[NBINS];
    __shared__ int   s_nsurv, s_tbin;
    __shared__ unsigned long long sel_key[P_];

    const int tid  = threadIdx.x;
    const int lane = tid & 31;
    const int wid  = tid >> 5;

    const int nc = min(g_count[bk], CAND_CAP);

    s_hist[tid] = 0;
    if (tid == 0) s_nsurv = 0;
    __syncthreads();

    // pass 1: histogram of candidate scores
    for (int i = tid; i < nc; i += NT1) {
        unsigned long long k = g_keys[bk][i];
        float sc = __uint_as_float((unsigned)(k >> 32));
        atomicAdd(&s_hist[min(NBINS - 1, (int)(sc * (float)NBINS))], 1);
    }
    __syncthreads();

    if (tid == 0) {
        int need = min(P_, nc);
        int cum = 0, t = 0;
        if (need > 0) {
            for (int b = NBINS - 1; b >= 0; --b) {
                cum += s_hist[b];
                if (cum >= need) { t = b; break; }
            }
        }
        s_tbin = t;
    }
    __syncthreads();
    const int tbin = s_tbin;

    // pass 2: filter survivors (keys now L2-hot)
    for (int i = tid; i < nc; i += NT1) {
        unsigned long long k = g_keys[bk][i];
        float sc = __uint_as_float((unsigned)(k >> 32));
        int bin = min(NBINS - 1, (int)(sc * (float)NBINS));
        if (bin >= tbin) {
            int slot = atomicAdd(&s_nsurv, 1);
            if (slot < SURV_CAP) surv[slot] = k;
        }
    }
    __syncthreads();

    // warp 0: 20 argmax rounds (top_k semantics: score desc, index asc)
    if (wid == 0) {
        unsigned long long* list;
        int len;
        if (s_nsurv <= SURV_CAP) { list = surv; len = s_nsurv; }
        else                     { list = &g_keys[bk][0]; len = nc; } // fallback

        for (int r = 0; r < P_; r++) {
            unsigned long long bkey = 0ull;
            int bidx = -1;
            for (int i = lane; i < len; i += 32) {
                unsigned long long k = list[i];
                if (k > bkey) { bkey = k; bidx = i; }
            }
            #pragma unroll
            for (int o = 16; o > 0; o >>= 1) {
                unsigned long long ok = __shfl_down_sync(0xffffffffu, bkey, o);
                int oi = __shfl_down_sync(0xffffffffu, bidx, o);
                if (ok > bkey) { bkey = ok; bidx = oi; }
            }
            if (lane == 0) {
                sel_key[r] = bkey;
                if (bidx >= 0) list[bidx] = 0ull;
            }
            __syncwarp();
        }
    }
    __syncthreads();

    if (tid < P_) {
        unsigned long long k = sel_key[tid];
        float px = 0.0f, py = 0.0f, so = 0.0f;
        if (k != 0ull) {
            float sc = __uint_as_float((unsigned)(k >> 32));
            int p = (int)(0xFFFFFFFFu - (unsigned)(k & 0xFFFFFFFFull));
            int y = p / W_;
            int x = p - y * W_;
            float ddx = 0.0f, ddy = 0.0f;
            if (x > 0 && x < W_-1 && y > 0 && y < H_-1) {
                float c  = h[p];
                float rr = h[p + 1],  ll = h[p - 1];
                float dd = h[p + W_], uu = h[p - W_];
                float dx  = 0.5f * (rr - ll);
                float dxx = (rr + ll) - 2.0f * c;
                if (dxx != 0.0f) dx = dx / (-dxx);
                float dy  = 0.5f * (dd - uu);
                float dyy = (dd + uu) - 2.0f * c;
                if (dyy != 0.0f) dy = dy / (-dyy);
                ddx = dx; ddy = dy;
            }
            px = (float)x + ddx;
            py = (float)y + ddy;
            so = sc;
        }
        float* o = out_peaks + ((size_t)bk * P_ + tid) * 3;
        o[0] = px; o[1] = py; o[2] = so;
    }

    // reset scratch for the next (graph-replayed) run
    if (tid == 0) g_count[bk] = 0;
}

// ---------------------------------------------------------------------------
// Kernel 2: flat one-thread-per-cell PAF line-integral scoring.
// ---------------------------------------------------------------------------
#define NT2 256
#define NCELLS (B_*C_*P_*P_)
__global__ __launch_bounds__(NT2)
void conn_kernel(const float* __restrict__ paf,
                 const float* __restrict__ peaks,
                 float* __restrict__ conn)
{
    const int gid = blockIdx.x * NT2 + threadIdx.x;
    if (gid >= NCELLS) return;

    int j = gid % P_;
    int t = gid / P_;
    int i = t % P_;  t /= P_;
    int c = t % C_;
    int b = t / C_;

    const float* pkA = peaks + (((size_t)b * K_ + SKEL_A[c]) * P_ + i) * 3;
    const float* pkB = peaks + (((size_t)b * K_ + SKEL_B[c]) * P_ + j) * 3;
    float axi = __ldg(pkA + 0), ayi = __ldg(pkA + 1), sa = __ldg(pkA + 2);
    float bxj = __ldg(pkB + 0), byj = __ldg(pkB + 1), sb = __ldg(pkB + 2);

    const float* __restrict__ pafx = paf + ((size_t)b * (2*C_) + 2*c) * HW_;
    const float* __restrict__ pafy = pafx + HW_;

    const float delta = 1.0f / 9.0f;

    float dxl = bxj - axi;
    float dyl = byj - ayi;
    float norm = sqrtf(dxl*dxl + dyl*dyl) + 1e-8f;
    float vx = dxl / norm, vy = dyl / norm;

    int   idx[S_];
    bool  inb[S_];
    #pragma unroll
    for (int s = 0; s < S_; s++) {
        float t2 = (s == S_-1) ? 1.0f : (float)s * delta;
        float xs = axi + dxl * t2;
        float ys = ayi + dyl * t2;
        int xi = __float2int_rz(xs);
        int yi = __float2int_rz(ys);
        inb[s] = (xi >= 0) & (xi < W_) & (yi >= 0) & (yi < H_);
        int xc = min(max(xi, 0), W_ - 1);
        int yc = min(max(yi, 0), H_ - 1);
        idx[s] = yc * W_ + xc;
    }

    float pxv[S_], pyv[S_];
    #pragma unroll
    for (int s = 0; s < S_; s++) pxv[s] = __ldg(pafx + idx[s]);
    #pragma unroll
    for (int s = 0; s < S_; s++) pyv[s] = __ldg(pafy + idx[s]);

    float cnt = 0.0f, sum = 0.0f, cntp = 0.0f;
    #pragma unroll
    for (int s = 0; s < S_; s++) {
        float vs = pxv[s] * vx + pyv[s] * vy;
        if (inb[s]) {
            cnt += 1.0f;
            sum += vs;
            if (vs > PAF_SCORE_THRESH) cntp += 1.0f;
        }
    }

    float denom = fmaxf(cnt, 1.0f);
    float mean  = sum / denom;
    float ratio = cntp / denom;
    bool ok = (cnt > 0.0f) && (mean > 0.0f) && (ratio > PAF_COUNT_THRESH)
              && (sa > PEAK_THRESH) && (sb > PEAK_THRESH);
    conn[gid] = ok ? (mean + 0.5f * (sa + sb)) : 0.0f;
}

// ---------------------------------------------------------------------------
extern "C" void kernel_launch(void* const* d_in, const int* in_sizes, int n_in,
                              void* d_out, int out_size)
{
    const float* heat = (const float*)d_in[0];
    const float* paf  = (const float*)d_in[1];
    if (n_in >= 2 && in_sizes[0] == B_ * 2 * C_ * HW_ && in_sizes[1] == B_ * K_ * HW_) {
        heat = (const float*)d_in[1];
        paf  = (const float*)d_in[0];
    }

    float* out_peaks = (float*)d_out;                      // B*K*P*3
    float* out_conn  = out_peaks + (size_t)B_ * K_ * P_ * 3;

    dim3 g1(H_ / CTAROWS, NCH);
    dim3 b1(QX, TY);
    peaks_scan<<<g1, b1>>>(heat);

    peaks_select<<<NCH, NT1>>>(heat, out_peaks);

    conn_kernel<<<(NCELLS + NT2 - 1) / NT2, NT2>>>(paf, out_peaks, out_conn);
}